// round 5
// baseline (speedup 1.0000x reference)
#include <cuda_runtime.h>
#include <math.h>
#include <float.h>

#define B_ 4
#define T_ 24
#define N_ 1024
#define F_ 128
#define H_ (B_*T_)
#define FRONT_T_ 12
#define ROWS_TOT (H_*N_)
#define LDP 132
#define EPS_ 1e-5f

__device__ __align__(128) float g_Q[(size_t)H_*N_*F_];
__device__ __align__(128) float g_K[(size_t)H_*N_*F_];
__device__ __align__(128) float g_V[(size_t)H_*N_*F_];
__device__ __align__(128) float g_AO[(size_t)H_*N_*F_];
__device__ float g_colsum[B_*N_];
__device__ int g_ylast[B_];

// ---- K0: zero colsum (graph replays) ----
__global__ void k_zero() {
    int i = blockIdx.x*256 + threadIdx.x;
    if (i < B_*N_) g_colsum[i] = 0.f;
}

// ---- K1: QKV = X @ W^T + b ----
__global__ __launch_bounds__(256,2) void k_qkv(const float* __restrict__ X,
                                               const float* __restrict__ W,
                                               const float* __restrict__ bias) {
    extern __shared__ float sm[];
    float* As = sm; float* Ws = sm + 64*LDP;
    const int rb = blockIdx.x*64, cb = blockIdx.y*64, tid = threadIdx.x;
    #pragma unroll
    for (int j = 0; j < 8; j++) {
        int idx = tid + j*256, r = idx>>5, f4 = idx&31;
        *reinterpret_cast<float4*>(&As[r*LDP+f4*4]) =
            reinterpret_cast<const float4*>(X)[(size_t)(rb+r)*32+f4];
        *reinterpret_cast<float4*>(&Ws[r*LDP+f4*4]) =
            reinterpret_cast<const float4*>(W)[(size_t)(cb+r)*32+f4];
    }
    __syncthreads();
    const int tx = tid&15, ty = tid>>4;
    float acc[4][4];
    #pragma unroll
    for (int i=0;i<4;i++)
        #pragma unroll
        for (int j=0;j<4;j++) acc[i][j]=0.f;
    for (int k = 0; k < 128; k++) {
        float a[4], w[4];
        #pragma unroll
        for (int i=0;i<4;i++) a[i] = As[(ty*4+i)*LDP+k];
        #pragma unroll
        for (int j=0;j<4;j++) w[j] = Ws[(j*16+tx)*LDP+k];
        #pragma unroll
        for (int i=0;i<4;i++)
            #pragma unroll
            for (int j=0;j<4;j++) acc[i][j] += a[i]*w[j];
    }
    #pragma unroll
    for (int i=0;i<4;i++) {
        int row = rb + ty*4 + i;
        #pragma unroll
        for (int j=0;j<4;j++) {
            int col = cb + j*16 + tx;
            float v = acc[i][j] + bias[col];
            float* dst = (col < 128) ? g_Q : (col < 256 ? g_K : g_V);
            dst[(size_t)row*F_ + (col&127)] = v;
        }
    }
}

// ---- K2: softmax column sums, t = T-1 only ----
__global__ __launch_bounds__(256) void k_colsum() {
    extern __shared__ float sm[];
    float* Ss = sm;                 // [16][1024]
    float* Qs = sm + 16*1024;       // [16][LDP]
    float* Ks = Qs + 16*LDP;        // [64][LDP]
    const int b = blockIdx.y, h = b*T_ + (T_-1);
    const int rb = blockIdx.x*16, tid = threadIdx.x;
    const float* Qh = g_Q + (size_t)h*N_*F_;
    const float* Kh = g_K + (size_t)h*N_*F_;
    #pragma unroll
    for (int j = 0; j < 2; j++) {
        int idx = tid + j*256, r = idx>>5, f4 = idx&31;
        *reinterpret_cast<float4*>(&Qs[r*LDP+f4*4]) =
            reinterpret_cast<const float4*>(Qh)[(size_t)(rb+r)*32+f4];
    }
    const int r = tid>>4, cg = tid&15;
    const float scale = 0.08838834764831845f;
    for (int kt = 0; kt < 16; kt++) {
        __syncthreads();
        #pragma unroll
        for (int j = 0; j < 8; j++) {
            int idx = tid + j*256, rr = idx>>5, f4 = idx&31;
            *reinterpret_cast<float4*>(&Ks[rr*LDP+f4*4]) =
                reinterpret_cast<const float4*>(Kh)[(size_t)(kt*64+rr)*32+f4];
        }
        __syncthreads();
        float acc[4] = {0.f,0.f,0.f,0.f};
        for (int k = 0; k < 128; k++) {
            float q = Qs[r*LDP+k];
            #pragma unroll
            for (int jj=0;jj<4;jj++) acc[jj] += q*Ks[(jj*16+cg)*LDP+k];
        }
        #pragma unroll
        for (int jj=0;jj<4;jj++) Ss[r*1024 + kt*64 + jj*16 + cg] = acc[jj]*scale;
    }
    __syncthreads();
    float m = -FLT_MAX;
    for (int s = 0; s < 64; s++) m = fmaxf(m, Ss[r*1024 + s*16 + cg]);
    #pragma unroll
    for (int o=8;o>0;o>>=1) m = fmaxf(m, __shfl_xor_sync(0xffffffffu, m, o));
    float l = 0.f;
    for (int s = 0; s < 64; s++) {
        float p = __expf(Ss[r*1024 + s*16 + cg] - m);
        Ss[r*1024 + s*16 + cg] = p; l += p;
    }
    #pragma unroll
    for (int o=8;o>0;o>>=1) l += __shfl_xor_sync(0xffffffffu, l, o);
    float inv = 1.f/l;
    for (int s = 0; s < 64; s++) Ss[r*1024 + s*16 + cg] *= inv;
    __syncthreads();
    #pragma unroll
    for (int j = 0; j < 4; j++) {
        int c = tid + j*256;
        float ssum = 0.f;
        #pragma unroll
        for (int rr=0;rr<16;rr++) ssum += Ss[rr*1024 + c];
        atomicAdd(&g_colsum[b*N_ + c], ssum);
    }
}

// ---- K3: 3rd-smallest colsum index (jax tie rule: lower index wins) ----
__global__ void k_ylast() {
    __shared__ float vals[N_]; __shared__ float rv[256];
    __shared__ int ri[256]; __shared__ int excl[3];
    const int b = blockIdx.x, tid = threadIdx.x;
    #pragma unroll
    for (int j=0;j<4;j++) vals[tid+j*256] = g_colsum[b*N_ + tid + j*256];
    __syncthreads();
    for (int round = 0; round < 3; round++) {
        float bv = FLT_MAX; int bi = N_;
        #pragma unroll
        for (int j=0;j<4;j++) {
            int i = tid + j*256; bool skip = false;
            for (int e=0;e<round;e++) if (excl[e]==i) skip = true;
            if (!skip) { float v = vals[i];
                if (v < bv || (v==bv && i<bi)) { bv=v; bi=i; } }
        }
        rv[tid]=bv; ri[tid]=bi; __syncthreads();
        for (int st=128; st>0; st>>=1) {
            if (tid < st) {
                float v2=rv[tid+st]; int i2=ri[tid+st];
                if (v2<rv[tid] || (v2==rv[tid] && i2<ri[tid])) { rv[tid]=v2; ri[tid]=i2; }
            }
            __syncthreads();
        }
        if (tid==0) excl[round] = ri[0];
        __syncthreads();
    }
    if (tid==0) g_ylast[b] = excl[2];
}

// ---- K4: mixup row y_last of V for t < FRONT_T ----
__global__ void k_mixup() {
    const int b = blockIdx.x / FRONT_T_, t = blockIdx.x % FRONT_T_, f = threadIdx.x;
    const int y = g_ylast[b];
    const int ys = max(y-1,0), ye = min(y+2,N_);
    float s = 0.f;
    for (int n = ys; n < ye; n++) s += g_V[(((size_t)(b*T_+t))*N_+n)*F_+f];
    float m = s/(float)(ye-ys);
    g_V[(((size_t)(b*T_+t))*N_+y)*F_+f] = fminf(fmaxf(truncf(m),0.f),255.f);
}

// ---- K5: flash attention fp32, BM=BN=64, P aliases K smem ----
__global__ __launch_bounds__(256,2) void k_attn() {
    extern __shared__ float sm[];
    float* Qs = sm; float* Ks = sm + 64*LDP; float* Vs = sm + 2*64*LDP;
    const int h = blockIdx.y, qb = blockIdx.x*64;
    const float* Qh = g_Q + (size_t)h*N_*F_;
    const float* Kh = g_K + (size_t)h*N_*F_;
    const float* Vh = g_V + (size_t)h*N_*F_;
    float* Oh = g_AO + (size_t)h*N_*F_;
    const int tid = threadIdx.x, tx = tid&15, ty = tid>>4;
    #pragma unroll
    for (int j = 0; j < 8; j++) {
        int idx = tid + j*256, r = idx>>5, f4 = idx&31;
        *reinterpret_cast<float4*>(&Qs[r*LDP+f4*4]) =
            reinterpret_cast<const float4*>(Qh)[(size_t)(qb+r)*32+f4];
    }
    float O[4][8]; float mrow[4], lrow[4];
    #pragma unroll
    for (int i=0;i<4;i++) { mrow[i]=-FLT_MAX; lrow[i]=0.f;
        #pragma unroll
        for (int c=0;c<8;c++) O[i][c]=0.f; }
    const float scale = 0.08838834764831845f;
    for (int kt = 0; kt < 16; kt++) {
        __syncthreads();
        #pragma unroll
        for (int j = 0; j < 8; j++) {
            int idx = tid + j*256, r = idx>>5, f4 = idx&31;
            *reinterpret_cast<float4*>(&Ks[r*LDP+f4*4]) =
                reinterpret_cast<const float4*>(Kh)[(size_t)(kt*64+r)*32+f4];
            *reinterpret_cast<float4*>(&Vs[r*128+f4*4]) =
                reinterpret_cast<const float4*>(Vh)[(size_t)(kt*64+r)*32+f4];
        }
        __syncthreads();
        float s[4][4];
        #pragma unroll
        for (int i=0;i<4;i++)
            #pragma unroll
            for (int j=0;j<4;j++) s[i][j]=0.f;
        for (int k = 0; k < 128; k++) {
            float a[4], bv[4];
            #pragma unroll
            for (int i=0;i<4;i++) a[i] = Qs[(ty*4+i)*LDP+k];
            #pragma unroll
            for (int j=0;j<4;j++) bv[j] = Ks[(j*16+tx)*LDP+k];
            #pragma unroll
            for (int i=0;i<4;i++)
                #pragma unroll
                for (int j=0;j<4;j++) s[i][j] += a[i]*bv[j];
        }
        #pragma unroll
        for (int i=0;i<4;i++) {
            float rm = -FLT_MAX;
            #pragma unroll
            for (int j=0;j<4;j++) { s[i][j] *= scale; rm = fmaxf(rm, s[i][j]); }
            #pragma unroll
            for (int o=8;o>0;o>>=1) rm = fmaxf(rm, __shfl_xor_sync(0xffffffffu, rm, o));
            float nm = fmaxf(mrow[i], rm);
            float corr = __expf(mrow[i] - nm);
            mrow[i] = nm; lrow[i] *= corr;
            #pragma unroll
            for (int c=0;c<8;c++) O[i][c] *= corr;
            float rs = 0.f;
            #pragma unroll
            for (int j=0;j<4;j++) { float p = __expf(s[i][j]-nm); s[i][j]=p; rs += p; }
            #pragma unroll
            for (int o=8;o>0;o>>=1) rs += __shfl_xor_sync(0xffffffffu, rs, o);
            lrow[i] += rs;
        }
        __syncthreads();
        float* Ps = Ks;
        #pragma unroll
        for (int i=0;i<4;i++)
            #pragma unroll
            for (int j=0;j<4;j++) Ps[(ty*4+i)*68 + j*16+tx] = s[i][j];
        __syncthreads();
        #pragma unroll 4
        for (int j = 0; j < 64; j++) {
            float p0 = Ps[(ty*4+0)*68+j], p1 = Ps[(ty*4+1)*68+j];
            float p2 = Ps[(ty*4+2)*68+j], p3 = Ps[(ty*4+3)*68+j];
            float4 v0 = *reinterpret_cast<float4*>(&Vs[j*128 + tx*8]);
            float4 v1 = *reinterpret_cast<float4*>(&Vs[j*128 + tx*8 + 4]);
            O[0][0]+=p0*v0.x; O[0][1]+=p0*v0.y; O[0][2]+=p0*v0.z; O[0][3]+=p0*v0.w;
            O[0][4]+=p0*v1.x; O[0][5]+=p0*v1.y; O[0][6]+=p0*v1.z; O[0][7]+=p0*v1.w;
            O[1][0]+=p1*v0.x; O[1][1]+=p1*v0.y; O[1][2]+=p1*v0.z; O[1][3]+=p1*v0.w;
            O[1][4]+=p1*v1.x; O[1][5]+=p1*v1.y; O[1][6]+=p1*v1.z; O[1][7]+=p1*v1.w;
            O[2][0]+=p2*v0.x; O[2][1]+=p2*v0.y; O[2][2]+=p2*v0.z; O[2][3]+=p2*v0.w;
            O[2][4]+=p2*v1.x; O[2][5]+=p2*v1.y; O[2][6]+=p2*v1.z; O[2][7]+=p2*v1.w;
            O[3][0]+=p3*v0.x; O[3][1]+=p3*v0.y; O[3][2]+=p3*v0.z; O[3][3]+=p3*v0.w;
            O[3][4]+=p3*v1.x; O[3][5]+=p3*v1.y; O[3][6]+=p3*v1.z; O[3][7]+=p3*v1.w;
        }
    }
    #pragma unroll
    for (int i=0;i<4;i++) {
        float inv = 1.f/lrow[i];
        size_t row = qb + ty*4 + i;
        float4 o0 = make_float4(O[i][0]*inv,O[i][1]*inv,O[i][2]*inv,O[i][3]*inv);
        float4 o1 = make_float4(O[i][4]*inv,O[i][5]*inv,O[i][6]*inv,O[i][7]*inv);
        *reinterpret_cast<float4*>(&Oh[row*F_ + tx*8]) = o0;
        *reinterpret_cast<float4*>(&Oh[row*F_ + tx*8 + 4]) = o1;
    }
}

// ---- K6: FF(gelu-erf) + residual + LayerNorm; weights resident in smem ----
__global__ __launch_bounds__(256) void k_ffln(const float* __restrict__ Xin,
        const float* __restrict__ W1, const float* __restrict__ b1,
        const float* __restrict__ W2, const float* __restrict__ b2,
        const float* __restrict__ lg, const float* __restrict__ lb,
        float* __restrict__ out) {
    extern __shared__ float sm[];
    float* W1t = sm; float* W2t = sm + 16384; float* rowb = sm + 32768;
    const int tid = threadIdx.x;
    for (int i = tid; i < 16384; i += 256) {
        int j = i>>7, k = i&127;
        W1t[k*128+j] = W1[i]; W2t[k*128+j] = W2[i];
    }
    __syncthreads();
    const int w = tid>>5, l = tid&31;
    float4 b1v = reinterpret_cast<const float4*>(b1)[l];
    float4 b2v = reinterpret_cast<const float4*>(b2)[l];
    float4 gv  = reinterpret_cast<const float4*>(lg)[l];
    float4 bbv = reinterpret_cast<const float4*>(lb)[l];
    const float is2 = 0.7071067811865475f;
    for (int tile = blockIdx.x; tile < ROWS_TOT/16; tile += gridDim.x) {
        size_t r0 = (size_t)tile*16 + w*2, r1 = r0 + 1;
        float* ra = rowb + (w*2)*128; float* rb = ra + 128;
        reinterpret_cast<float4*>(ra)[l] = reinterpret_cast<const float4*>(g_AO)[r0*32+l];
        reinterpret_cast<float4*>(rb)[l] = reinterpret_cast<const float4*>(g_AO)[r1*32+l];
        __syncwarp();
        float4 ha = b1v, hb = b1v;
        for (int k = 0; k < 128; k++) {
            float xa = ra[k], xb = rb[k];
            float4 wv = *reinterpret_cast<float4*>(&W1t[k*128 + l*4]);
            ha.x += xa*wv.x; ha.y += xa*wv.y; ha.z += xa*wv.z; ha.w += xa*wv.w;
            hb.x += xb*wv.x; hb.y += xb*wv.y; hb.z += xb*wv.z; hb.w += xb*wv.w;
        }
        ha.x = 0.5f*ha.x*(1.f+erff(ha.x*is2)); ha.y = 0.5f*ha.y*(1.f+erff(ha.y*is2));
        ha.z = 0.5f*ha.z*(1.f+erff(ha.z*is2)); ha.w = 0.5f*ha.w*(1.f+erff(ha.w*is2));
        hb.x = 0.5f*hb.x*(1.f+erff(hb.x*is2)); hb.y = 0.5f*hb.y*(1.f+erff(hb.y*is2));
        hb.z = 0.5f*hb.z*(1.f+erff(hb.z*is2)); hb.w = 0.5f*hb.w*(1.f+erff(hb.w*is2));
        __syncwarp();
        reinterpret_cast<float4*>(ra)[l] = ha;
        reinterpret_cast<float4*>(rb)[l] = hb;
        __syncwarp();
        float4 oa = b2v, ob = b2v;
        for (int k = 0; k < 128; k++) {
            float xa = ra[k], xb = rb[k];
            float4 wv = *reinterpret_cast<float4*>(&W2t[k*128 + l*4]);
            oa.x += xa*wv.x; oa.y += xa*wv.y; oa.z += xa*wv.z; oa.w += xa*wv.w;
            ob.x += xb*wv.x; ob.y += xb*wv.y; ob.z += xb*wv.z; ob.w += xb*wv.w;
        }
        float4 ia = reinterpret_cast<const float4*>(Xin)[r0*32+l];
        float4 ib = reinterpret_cast<const float4*>(Xin)[r1*32+l];
        oa.x += ia.x; oa.y += ia.y; oa.z += ia.z; oa.w += ia.w;
        ob.x += ib.x; ob.y += ib.y; ob.z += ib.z; ob.w += ib.w;
        float sa = oa.x+oa.y+oa.z+oa.w;
        float qa = oa.x*oa.x+oa.y*oa.y+oa.z*oa.z+oa.w*oa.w;
        float sb = ob.x+ob.y+ob.z+ob.w;
        float qb2 = ob.x*ob.x+ob.y*ob.y+ob.z*ob.z+ob.w*ob.w;
        #pragma unroll
        for (int o=16;o>0;o>>=1) {
            sa += __shfl_xor_sync(0xffffffffu, sa, o);
            qa += __shfl_xor_sync(0xffffffffu, qa, o);
            sb += __shfl_xor_sync(0xffffffffu, sb, o);
            qb2 += __shfl_xor_sync(0xffffffffu, qb2, o);
        }
        float mua = sa*(1.f/128.f), mub = sb*(1.f/128.f);
        float rsa = rsqrtf(fmaxf(qa*(1.f/128.f) - mua*mua, 0.f) + EPS_);
        float rsb = rsqrtf(fmaxf(qb2*(1.f/128.f) - mub*mub, 0.f) + EPS_);
        float4 za, zb;
        za.x = (oa.x-mua)*rsa*gv.x + bbv.x; za.y = (oa.y-mua)*rsa*gv.y + bbv.y;
        za.z = (oa.z-mua)*rsa*gv.z + bbv.z; za.w = (oa.w-mua)*rsa*gv.w + bbv.w;
        zb.x = (ob.x-mub)*rsb*gv.x + bbv.x; zb.y = (ob.y-mub)*rsb*gv.y + bbv.y;
        zb.z = (ob.z-mub)*rsb*gv.z + bbv.z; zb.w = (ob.w-mub)*rsb*gv.w + bbv.w;
        reinterpret_cast<float4*>(out)[r0*32+l] = za;
        reinterpret_cast<float4*>(out)[r1*32+l] = zb;
    }
}

extern "C" void kernel_launch(void* const* d_in, const int* in_sizes, int n_in,
                              void* d_out, int out_size) {
    const float* input = (const float*)d_in[0];
    const float* W_xff = (const float*)d_in[1];
    const float* b_xff = (const float*)d_in[2];
    const float* W_ff1 = (const float*)d_in[3];
    const float* b_ff1 = (const float*)d_in[4];
    const float* W_ff2 = (const float*)d_in[5];
    const float* b_ff2 = (const float*)d_in[6];
    const float* ln_g  = (const float*)d_in[7];
    const float* ln_b  = (const float*)d_in[8];
    float* out = (float*)d_out;

    const int smQKV  = 2*64*LDP*4;                 // 67584
    const int smCOL  = (16*1024 + 16*LDP + 64*LDP)*4;  // 107776
    const int smATT  = (2*64*LDP + 64*128)*4;      // 100352
    const int smFF   = (32768 + 16*128)*4;         // 139264
    cudaFuncSetAttribute(k_qkv,    cudaFuncAttributeMaxDynamicSharedMemorySize, smQKV);
    cudaFuncSetAttribute(k_colsum, cudaFuncAttributeMaxDynamicSharedMemorySize, smCOL);
    cudaFuncSetAttribute(k_attn,   cudaFuncAttributeMaxDynamicSharedMemorySize, smATT);
    cudaFuncSetAttribute(k_ffln,   cudaFuncAttributeMaxDynamicSharedMemorySize, smFF);

    k_zero<<<16, 256>>>();
    k_qkv<<<dim3(ROWS_TOT/64, 6), 256, smQKV>>>(input, W_xff, b_xff);
    k_colsum<<<dim3(N_/16, B_), 256, smCOL>>>();
    k_ylast<<<B_, 256>>>();
    k_mixup<<<B_*FRONT_T_, F_>>>();
    k_attn<<<dim3(N_/64, H_), 256, smATT>>>();
    k_ffln<<<592, 256, smFF>>>(input, W_ff1, b_ff1, W_ff2, b_ff2, ln_g, ln_b, out);
}

// round 6
// speedup vs baseline: 1.1550x; 1.1550x over previous
#include <cuda_runtime.h>
#include <math.h>
#include <float.h>

#define B_ 4
#define T_ 24
#define N_ 1024
#define F_ 128
#define H_ (B_*T_)
#define FRONT_T_ 12
#define ROWS_TOT (H_*N_)
#define LDP 132     // legacy stride (k_colsum)
#define LDT 134     // packed-kernel stride: 134 % 32 == 6 -> conflict-free 16-lane row reads
#define EPS_ 1e-5f

typedef unsigned long long ull;

__device__ __align__(128) float g_Q[(size_t)H_*N_*F_];
__device__ __align__(128) float g_K[(size_t)H_*N_*F_];
__device__ __align__(128) float g_V[(size_t)H_*N_*F_];
__device__ __align__(128) float g_AO[(size_t)H_*N_*F_];
__device__ float g_colsum[B_*N_];
__device__ int g_ylast[B_];

// ---- packed f32x2 helpers (sm_103a FFMA2 path) ----
__device__ __forceinline__ void ffma2(ull &d, ull a, ull b) {
    asm("fma.rn.f32x2 %0, %1, %2, %0;" : "+l"(d) : "l"(a), "l"(b));
}
__device__ __forceinline__ void mul2(ull &d, ull a) {
    asm("mul.rn.f32x2 %0, %0, %1;" : "+l"(d) : "l"(a));
}
__device__ __forceinline__ ull bcast2(float p) {
    ull r; asm("mov.b64 %0, {%1, %1};" : "=l"(r) : "f"(p)); return r;
}
__device__ __forceinline__ float2 asf2(ull v) {
    float2 f; asm("mov.b64 {%0, %1}, %2;" : "=f"(f.x), "=f"(f.y) : "l"(v)); return f;
}

// load a 64x128 float tile from gmem (row-major, rows base..base+63) into smem
// with row stride LDT, via float4 gmem reads + float2 smem stores.
__device__ __forceinline__ void load_tile_134(float* dst, const float* src,
                                              size_t base, int tid) {
    #pragma unroll
    for (int jj = 0; jj < 8; jj++) {
        int idx = tid + jj*256, r = idx>>5, f4 = idx&31;
        float4 v = reinterpret_cast<const float4*>(src)[(base + r)*32 + f4];
        float* d = &dst[r*LDT + f4*4];
        *reinterpret_cast<float2*>(d)   = make_float2(v.x, v.y);
        *reinterpret_cast<float2*>(d+2) = make_float2(v.z, v.w);
    }
}

// ---- K0: zero colsum (graph replays) ----
__global__ void k_zero() {
    int i = blockIdx.x*256 + threadIdx.x;
    if (i < B_*N_) g_colsum[i] = 0.f;
}

// ---- K1: QKV = X @ W^T + b  (FFMA2, packed along k) ----
__global__ __launch_bounds__(256,2) void k_qkv(const float* __restrict__ X,
                                               const float* __restrict__ W,
                                               const float* __restrict__ bias) {
    extern __shared__ float sm[];
    float* As = sm; float* Ws = sm + 64*LDT;
    const int rb = blockIdx.x*64, cb = blockIdx.y*64, tid = threadIdx.x;
    load_tile_134(As, X, (size_t)rb, tid);
    load_tile_134(Ws, W, (size_t)cb, tid);
    __syncthreads();
    const int tx = tid&15, ty = tid>>4;
    ull acc2[4][4];
    #pragma unroll
    for (int i=0;i<4;i++)
        #pragma unroll
        for (int j=0;j<4;j++) acc2[i][j]=0ull;
    #pragma unroll 8
    for (int k2 = 0; k2 < 64; k2++) {
        ull a2[4], b2[4];
        #pragma unroll
        for (int i=0;i<4;i++) a2[i] = *reinterpret_cast<const ull*>(&As[(ty*4+i)*LDT + 2*k2]);
        #pragma unroll
        for (int j=0;j<4;j++) b2[j] = *reinterpret_cast<const ull*>(&Ws[(j*16+tx)*LDT + 2*k2]);
        #pragma unroll
        for (int i=0;i<4;i++)
            #pragma unroll
            for (int j=0;j<4;j++) ffma2(acc2[i][j], a2[i], b2[j]);
    }
    #pragma unroll
    for (int i=0;i<4;i++) {
        int row = rb + ty*4 + i;
        #pragma unroll
        for (int j=0;j<4;j++) {
            int col = cb + j*16 + tx;
            float2 f = asf2(acc2[i][j]);
            float v = f.x + f.y + bias[col];
            float* dst = (col < 128) ? g_Q : (col < 256 ? g_K : g_V);
            dst[(size_t)row*F_ + (col&127)] = v;
        }
    }
}

// ---- K2: softmax column sums, t = T-1 only (unchanged) ----
__global__ __launch_bounds__(256) void k_colsum() {
    extern __shared__ float sm[];
    float* Ss = sm;                 // [16][1024]
    float* Qs = sm + 16*1024;       // [16][LDP]
    float* Ks = Qs + 16*LDP;        // [64][LDP]
    const int b = blockIdx.y, h = b*T_ + (T_-1);
    const int rb = blockIdx.x*16, tid = threadIdx.x;
    const float* Qh = g_Q + (size_t)h*N_*F_;
    const float* Kh = g_K + (size_t)h*N_*F_;
    #pragma unroll
    for (int j = 0; j < 2; j++) {
        int idx = tid + j*256, r = idx>>5, f4 = idx&31;
        *reinterpret_cast<float4*>(&Qs[r*LDP+f4*4]) =
            reinterpret_cast<const float4*>(Qh)[(size_t)(rb+r)*32+f4];
    }
    const int r = tid>>4, cg = tid&15;
    const float scale = 0.08838834764831845f;
    for (int kt = 0; kt < 16; kt++) {
        __syncthreads();
        #pragma unroll
        for (int j = 0; j < 8; j++) {
            int idx = tid + j*256, rr = idx>>5, f4 = idx&31;
            *reinterpret_cast<float4*>(&Ks[rr*LDP+f4*4]) =
                reinterpret_cast<const float4*>(Kh)[(size_t)(kt*64+rr)*32+f4];
        }
        __syncthreads();
        float acc[4] = {0.f,0.f,0.f,0.f};
        for (int k = 0; k < 128; k++) {
            float q = Qs[r*LDP+k];
            #pragma unroll
            for (int jj=0;jj<4;jj++) acc[jj] += q*Ks[(jj*16+cg)*LDP+k];
        }
        #pragma unroll
        for (int jj=0;jj<4;jj++) Ss[r*1024 + kt*64 + jj*16 + cg] = acc[jj]*scale;
    }
    __syncthreads();
    float m = -FLT_MAX;
    for (int s = 0; s < 64; s++) m = fmaxf(m, Ss[r*1024 + s*16 + cg]);
    #pragma unroll
    for (int o=8;o>0;o>>=1) m = fmaxf(m, __shfl_xor_sync(0xffffffffu, m, o));
    float l = 0.f;
    for (int s = 0; s < 64; s++) {
        float p = __expf(Ss[r*1024 + s*16 + cg] - m);
        Ss[r*1024 + s*16 + cg] = p; l += p;
    }
    #pragma unroll
    for (int o=8;o>0;o>>=1) l += __shfl_xor_sync(0xffffffffu, l, o);
    float inv = 1.f/l;
    for (int s = 0; s < 64; s++) Ss[r*1024 + s*16 + cg] *= inv;
    __syncthreads();
    #pragma unroll
    for (int j = 0; j < 4; j++) {
        int c = tid + j*256;
        float ssum = 0.f;
        #pragma unroll
        for (int rr=0;rr<16;rr++) ssum += Ss[rr*1024 + c];
        atomicAdd(&g_colsum[b*N_ + c], ssum);
    }
}

// ---- K3: 3rd-smallest colsum index (jax tie rule: lower index wins) ----
__global__ void k_ylast() {
    __shared__ float vals[N_]; __shared__ float rv[256];
    __shared__ int ri[256]; __shared__ int excl[3];
    const int b = blockIdx.x, tid = threadIdx.x;
    #pragma unroll
    for (int j=0;j<4;j++) vals[tid+j*256] = g_colsum[b*N_ + tid + j*256];
    __syncthreads();
    for (int round = 0; round < 3; round++) {
        float bv = FLT_MAX; int bi = N_;
        #pragma unroll
        for (int j=0;j<4;j++) {
            int i = tid + j*256; bool skip = false;
            for (int e=0;e<round;e++) if (excl[e]==i) skip = true;
            if (!skip) { float v = vals[i];
                if (v < bv || (v==bv && i<bi)) { bv=v; bi=i; } }
        }
        rv[tid]=bv; ri[tid]=bi; __syncthreads();
        for (int st=128; st>0; st>>=1) {
            if (tid < st) {
                float v2=rv[tid+st]; int i2=ri[tid+st];
                if (v2<rv[tid] || (v2==rv[tid] && i2<ri[tid])) { rv[tid]=v2; ri[tid]=i2; }
            }
            __syncthreads();
        }
        if (tid==0) excl[round] = ri[0];
        __syncthreads();
    }
    if (tid==0) g_ylast[b] = excl[2];
}

// ---- K4: mixup row y_last of V for t < FRONT_T ----
__global__ void k_mixup() {
    const int b = blockIdx.x / FRONT_T_, t = blockIdx.x % FRONT_T_, f = threadIdx.x;
    const int y = g_ylast[b];
    const int ys = max(y-1,0), ye = min(y+2,N_);
    float s = 0.f;
    for (int n = ys; n < ye; n++) s += g_V[(((size_t)(b*T_+t))*N_+n)*F_+f];
    float m = s/(float)(ye-ys);
    g_V[(((size_t)(b*T_+t))*N_+y)*F_+f] = fminf(fmaxf(truncf(m),0.f),255.f);
}

// ---- K5: flash attention, FFMA2 everywhere ----
// smem: Qs[64][134] | Ks[64][134] (aliased by Ps[64][68]) | Vs[64][128]
__global__ __launch_bounds__(256,2) void k_attn() {
    extern __shared__ float sm[];
    float* Qs = sm; float* Ks = sm + 64*LDT; float* Vs = sm + 2*64*LDT;
    const int h = blockIdx.y, qb = blockIdx.x*64;
    const float* Qh = g_Q + (size_t)h*N_*F_;
    const float* Kh = g_K + (size_t)h*N_*F_;
    const float* Vh = g_V + (size_t)h*N_*F_;
    float* Oh = g_AO + (size_t)h*N_*F_;
    const int tid = threadIdx.x, tx = tid&15, ty = tid>>4;
    load_tile_134(Qs, Qh, (size_t)qb, tid);

    ull O2[4][4];                 // lanes = cols (2tx+32cc, 2tx+32cc+1)
    float mrow[4], lrow[4];
    #pragma unroll
    for (int i=0;i<4;i++) { mrow[i]=-FLT_MAX; lrow[i]=0.f;
        #pragma unroll
        for (int c=0;c<4;c++) O2[i][c]=0ull; }
    const float scale = 0.08838834764831845f;

    for (int kt = 0; kt < 16; kt++) {
        __syncthreads();
        load_tile_134(Ks, Kh, (size_t)(kt*64), tid);
        #pragma unroll
        for (int jj = 0; jj < 8; jj++) {      // V tile, row-major stride 128
            int idx = tid + jj*256, r = idx>>5, f4 = idx&31;
            *reinterpret_cast<float4*>(&Vs[r*128+f4*4]) =
                reinterpret_cast<const float4*>(Vh)[(size_t)(kt*64+r)*32+f4];
        }
        __syncthreads();

        // S = Q @ K^T, packed along k
        ull acc2[4][4];
        #pragma unroll
        for (int i=0;i<4;i++)
            #pragma unroll
            for (int j=0;j<4;j++) acc2[i][j]=0ull;
        #pragma unroll 8
        for (int k2 = 0; k2 < 64; k2++) {
            ull a2[4], b2[4];
            #pragma unroll
            for (int i=0;i<4;i++) a2[i] = *reinterpret_cast<const ull*>(&Qs[(ty*4+i)*LDT + 2*k2]);
            #pragma unroll
            for (int j=0;j<4;j++) b2[j] = *reinterpret_cast<const ull*>(&Ks[(j*16+tx)*LDT + 2*k2]);
            #pragma unroll
            for (int i=0;i<4;i++)
                #pragma unroll
                for (int j=0;j<4;j++) ffma2(acc2[i][j], a2[i], b2[j]);
        }
        float s[4][4];
        #pragma unroll
        for (int i=0;i<4;i++)
            #pragma unroll
            for (int j=0;j<4;j++) { float2 f = asf2(acc2[i][j]); s[i][j] = f.x + f.y; }

        // online softmax update
        #pragma unroll
        for (int i=0;i<4;i++) {
            float rm = -FLT_MAX;
            #pragma unroll
            for (int j=0;j<4;j++) { s[i][j] *= scale; rm = fmaxf(rm, s[i][j]); }
            #pragma unroll
            for (int o=8;o>0;o>>=1) rm = fmaxf(rm, __shfl_xor_sync(0xffffffffu, rm, o));
            float nm = fmaxf(mrow[i], rm);
            float corr = __expf(mrow[i] - nm);
            mrow[i] = nm; lrow[i] *= corr;
            ull c2 = bcast2(corr);
            #pragma unroll
            for (int c=0;c<4;c++) mul2(O2[i][c], c2);
            float rs = 0.f;
            #pragma unroll
            for (int j=0;j<4;j++) { float p = __expf(s[i][j]-nm); s[i][j]=p; rs += p; }
            #pragma unroll
            for (int o=8;o>0;o>>=1) rs += __shfl_xor_sync(0xffffffffu, rs, o);
            lrow[i] += rs;
        }
        __syncthreads();
        float* Ps = Ks;                       // alias: P tile [64][68]
        #pragma unroll
        for (int i=0;i<4;i++)
            #pragma unroll
            for (int j=0;j<4;j++) Ps[(ty*4+i)*68 + j*16+tx] = s[i][j];
        __syncthreads();

        // O += P @ V, packed along output columns
        #pragma unroll 4
        for (int j2 = 0; j2 < 32; j2++) {
            float2 p01[4];
            #pragma unroll
            for (int i=0;i<4;i++)
                p01[i] = *reinterpret_cast<float2*>(&Ps[(ty*4+i)*68 + 2*j2]);
            ull v0[4], v1[4];
            #pragma unroll
            for (int c=0;c<4;c++) {
                v0[c] = *reinterpret_cast<const ull*>(&Vs[(2*j2  )*128 + 2*tx + 32*c]);
                v1[c] = *reinterpret_cast<const ull*>(&Vs[(2*j2+1)*128 + 2*tx + 32*c]);
            }
            #pragma unroll
            for (int i=0;i<4;i++) {
                ull pj0 = bcast2(p01[i].x), pj1 = bcast2(p01[i].y);
                #pragma unroll
                for (int c=0;c<4;c++) { ffma2(O2[i][c], pj0, v0[c]); ffma2(O2[i][c], pj1, v1[c]); }
            }
        }
    }

    #pragma unroll
    for (int i=0;i<4;i++) {
        float inv = 1.f/lrow[i];
        size_t row = qb + ty*4 + i;
        #pragma unroll
        for (int c=0;c<4;c++) {
            float2 f = asf2(O2[i][c]);
            *reinterpret_cast<float2*>(&Oh[row*F_ + 2*tx + 32*c]) =
                make_float2(f.x*inv, f.y*inv);
        }
    }
}

// ---- K6: FF(gelu-erf) + residual + LayerNorm; weights resident in smem ----
__global__ __launch_bounds__(256) void k_ffln(const float* __restrict__ Xin,
        const float* __restrict__ W1, const float* __restrict__ b1,
        const float* __restrict__ W2, const float* __restrict__ b2,
        const float* __restrict__ lg, const float* __restrict__ lb,
        float* __restrict__ out) {
    extern __shared__ float sm[];
    float* W1t = sm; float* W2t = sm + 16384; float* rowb = sm + 32768;
    const int tid = threadIdx.x;
    for (int i = tid; i < 16384; i += 256) {
        int j = i>>7, k = i&127;
        W1t[k*128+j] = W1[i]; W2t[k*128+j] = W2[i];
    }
    __syncthreads();
    const int w = tid>>5, l = tid&31;
    float4 b1v = reinterpret_cast<const float4*>(b1)[l];
    float4 b2v = reinterpret_cast<const float4*>(b2)[l];
    float4 gv  = reinterpret_cast<const float4*>(lg)[l];
    float4 bbv = reinterpret_cast<const float4*>(lb)[l];
    const float is2 = 0.7071067811865475f;
    for (int tile = blockIdx.x; tile < ROWS_TOT/16; tile += gridDim.x) {
        size_t r0 = (size_t)tile*16 + w*2, r1 = r0 + 1;
        float* ra = rowb + (w*2)*128; float* rb = ra + 128;
        reinterpret_cast<float4*>(ra)[l] = reinterpret_cast<const float4*>(g_AO)[r0*32+l];
        reinterpret_cast<float4*>(rb)[l] = reinterpret_cast<const float4*>(g_AO)[r1*32+l];
        __syncwarp();
        float4 ha = b1v, hb = b1v;
        for (int k = 0; k < 128; k++) {
            float xa = ra[k], xb = rb[k];
            float4 wv = *reinterpret_cast<float4*>(&W1t[k*128 + l*4]);
            ha.x += xa*wv.x; ha.y += xa*wv.y; ha.z += xa*wv.z; ha.w += xa*wv.w;
            hb.x += xb*wv.x; hb.y += xb*wv.y; hb.z += xb*wv.z; hb.w += xb*wv.w;
        }
        ha.x = 0.5f*ha.x*(1.f+erff(ha.x*is2)); ha.y = 0.5f*ha.y*(1.f+erff(ha.y*is2));
        ha.z = 0.5f*ha.z*(1.f+erff(ha.z*is2)); ha.w = 0.5f*ha.w*(1.f+erff(ha.w*is2));
        hb.x = 0.5f*hb.x*(1.f+erff(hb.x*is2)); hb.y = 0.5f*hb.y*(1.f+erff(hb.y*is2));
        hb.z = 0.5f*hb.z*(1.f+erff(hb.z*is2)); hb.w = 0.5f*hb.w*(1.f+erff(hb.w*is2));
        __syncwarp();
        reinterpret_cast<float4*>(ra)[l] = ha;
        reinterpret_cast<float4*>(rb)[l] = hb;
        __syncwarp();
        float4 oa = b2v, ob = b2v;
        for (int k = 0; k < 128; k++) {
            float xa = ra[k], xb = rb[k];
            float4 wv = *reinterpret_cast<float4*>(&W2t[k*128 + l*4]);
            oa.x += xa*wv.x; oa.y += xa*wv.y; oa.z += xa*wv.z; oa.w += xa*wv.w;
            ob.x += xb*wv.x; ob.y += xb*wv.y; ob.z += xb*wv.z; ob.w += xb*wv.w;
        }
        float4 ia = reinterpret_cast<const float4*>(Xin)[r0*32+l];
        float4 ib = reinterpret_cast<const float4*>(Xin)[r1*32+l];
        oa.x += ia.x; oa.y += ia.y; oa.z += ia.z; oa.w += ia.w;
        ob.x += ib.x; ob.y += ib.y; ob.z += ib.z; ob.w += ib.w;
        float sa = oa.x+oa.y+oa.z+oa.w;
        float qa = oa.x*oa.x+oa.y*oa.y+oa.z*oa.z+oa.w*oa.w;
        float sb = ob.x+ob.y+ob.z+ob.w;
        float qb2 = ob.x*ob.x+ob.y*ob.y+ob.z*ob.z+ob.w*ob.w;
        #pragma unroll
        for (int o=16;o>0;o>>=1) {
            sa += __shfl_xor_sync(0xffffffffu, sa, o);
            qa += __shfl_xor_sync(0xffffffffu, qa, o);
            sb += __shfl_xor_sync(0xffffffffu, sb, o);
            qb2 += __shfl_xor_sync(0xffffffffu, qb2, o);
        }
        float mua = sa*(1.f/128.f), mub = sb*(1.f/128.f);
        float rsa = rsqrtf(fmaxf(qa*(1.f/128.f) - mua*mua, 0.f) + EPS_);
        float rsb = rsqrtf(fmaxf(qb2*(1.f/128.f) - mub*mub, 0.f) + EPS_);
        float4 za, zb;
        za.x = (oa.x-mua)*rsa*gv.x + bbv.x; za.y = (oa.y-mua)*rsa*gv.y + bbv.y;
        za.z = (oa.z-mua)*rsa*gv.z + bbv.z; za.w = (oa.w-mua)*rsa*gv.w + bbv.w;
        zb.x = (ob.x-mub)*rsb*gv.x + bbv.x; zb.y = (ob.y-mub)*rsb*gv.y + bbv.y;
        zb.z = (ob.z-mub)*rsb*gv.z + bbv.z; zb.w = (ob.w-mub)*rsb*gv.w + bbv.w;
        reinterpret_cast<float4*>(out)[r0*32+l] = za;
        reinterpret_cast<float4*>(out)[r1*32+l] = zb;
    }
}

extern "C" void kernel_launch(void* const* d_in, const int* in_sizes, int n_in,
                              void* d_out, int out_size) {
    const float* input = (const float*)d_in[0];
    const float* W_xff = (const float*)d_in[1];
    const float* b_xff = (const float*)d_in[2];
    const float* W_ff1 = (const float*)d_in[3];
    const float* b_ff1 = (const float*)d_in[4];
    const float* W_ff2 = (const float*)d_in[5];
    const float* b_ff2 = (const float*)d_in[6];
    const float* ln_g  = (const float*)d_in[7];
    const float* ln_b  = (const float*)d_in[8];
    float* out = (float*)d_out;

    const int smQKV  = 2*64*LDT*4;                     // 68608
    const int smCOL  = (16*1024 + 16*LDP + 64*LDP)*4;  // 107776
    const int smATT  = (2*64*LDT + 64*128)*4;          // 101376
    const int smFF   = (32768 + 16*128)*4;             // 139264
    cudaFuncSetAttribute(k_qkv,    cudaFuncAttributeMaxDynamicSharedMemorySize, smQKV);
    cudaFuncSetAttribute(k_colsum, cudaFuncAttributeMaxDynamicSharedMemorySize, smCOL);
    cudaFuncSetAttribute(k_attn,   cudaFuncAttributeMaxDynamicSharedMemorySize, smATT);
    cudaFuncSetAttribute(k_ffln,   cudaFuncAttributeMaxDynamicSharedMemorySize, smFF);

    k_zero<<<16, 256>>>();
    k_qkv<<<dim3(ROWS_TOT/64, 6), 256, smQKV>>>(input, W_xff, b_xff);
    k_colsum<<<dim3(N_/16, B_), 256, smCOL>>>();
    k_ylast<<<B_, 256>>>();
    k_mixup<<<B_*FRONT_T_, F_>>>();
    k_attn<<<dim3(N_/64, H_), 256, smATT>>>();
    k_ffln<<<592, 256, smFF>>>(input, W_ff1, b_ff1, W_ff2, b_ff2, ln_g, ln_b, out);
}